// round 1
// baseline (speedup 1.0000x reference)
#include <cuda_runtime.h>
#include <math.h>

// Problem dims
#define B_   256
#define S_   200
#define T_   100
#define F_   10
#define E_   128
#define H_   256
#define G4   1024   // 4*H
#define P1_  512
#define P2_  128

// ---------------- scratch (device globals; no runtime alloc allowed) ----------------
__device__ float g_e   [S_*B_*E_];     // e transposed: [s][b][k]      (26 MB)
__device__ float g_Gx  [(size_t)S_*B_*G4];   // x-part + biases, gate-interleaved cols [s][b][n'] (210 MB)
__device__ float g_WihP[G4*E_];        // permuted rows: n' = 4*j+gate
__device__ float g_WhhP[G4*H_];
__device__ float g_biasP[G4];          // b_ih + b_hh, permuted
__device__ float g_h[2][B_*H_];        // ping-pong hidden state
__device__ float g_c[B_*H_];
__device__ float g_r[B_*G4];           // hN @ WhhP^T
__device__ float g_Hout[T_*B_*H_];     // rows = t*256+b
__device__ float g_Z1[(size_t)T_*B_*P1_];
__device__ float g_Z2[T_*B_*P2_];

__device__ __forceinline__ float sigmf(float x) { return 1.0f / (1.0f + expf(-x)); }

// ---------------- small prep kernels ----------------
__global__ void permute_weights(const float* __restrict__ Wih, const float* __restrict__ Whh,
                                const float* __restrict__ bih, const float* __restrict__ bhh)
{
    int np  = blockIdx.x;                 // 0..1023 (n')
    int src = (np & 3) * H_ + (np >> 2);  // gate*256 + unit
    int t   = threadIdx.x;                // 256 threads
    if (t < E_) g_WihP[np * E_ + t] = Wih[src * E_ + t];
    g_WhhP[np * H_ + t] = Whh[src * H_ + t];
    if (t == 0) g_biasP[np] = bih[src] + bhh[src];
}

__global__ void zero_hc()
{
    int i = blockIdx.x * 256 + threadIdx.x;
    if (i < B_ * H_) { g_h[0][i] = 0.0f; g_c[i] = 0.0f; }
}

// e[b][s][:] = mean_f emb[x[b][s][f]]; stored transposed as [s][b][k]
__global__ void embed_mean(const int* __restrict__ x, const float* __restrict__ emb)
{
    int row = blockIdx.x;            // b*S_ + s
    int b = row / S_, s = row % S_;
    const int* xi = x + row * F_;
    int k = threadIdx.x;             // 0..127
    float sum = 0.0f;
#pragma unroll
    for (int f = 0; f < F_; f++) sum += emb[(size_t)xi[f] * E_ + k];
    g_e[((size_t)s * B_ + b) * E_ + k] = sum * (1.0f / (float)F_);
}

// ---------------- generic fp32 GEMM: C = act(A @ op(B) + bias) ----------------
// BT=1 : B given as (N,K) row-major (weight (out,in)), C += A·B^T
// BT=0 : B given as (K,N) row-major,                  C += A·B
// tile 128x128, K-chunk 16, 256 threads, 8x8 per thread, register prefetch.
// Requires M%128==0, N%128==0, K%16==0 (true for all uses here).
template<int BT, int RELU>
__global__ void __launch_bounds__(256) gemm128(const float* __restrict__ A,
                                               const float* __restrict__ Bm,
                                               const float* __restrict__ bias,
                                               float* __restrict__ C,
                                               int M, int N, int K)
{
    __shared__ float As[16][132];
    __shared__ float Bs[16][132];

    const int tid  = threadIdx.x;
    const int m0   = blockIdx.y << 7;
    const int n0   = blockIdx.x << 7;
    const int arow = tid >> 2, acol = (tid & 3) << 2;   // 128x16 loader
    const int brow = tid >> 4, bcol = (tid & 15) << 3;  // 16x128 loader (NK case)
    const int mf   = (tid >> 4) << 3;                   // 8-row frag base
    const int nf   = (tid & 15) << 3;                   // 8-col frag base

    float acc[8][8];
#pragma unroll
    for (int i = 0; i < 8; i++)
#pragma unroll
        for (int j = 0; j < 8; j++) acc[i][j] = 0.0f;

    const float* Ap0 = A + (size_t)(m0 + arow) * K + acol;
    const float* Ap1 = Ap0 + (size_t)64 * K;
    const float* Bp0; const float* Bp1 = 0;
    float4 a0 = *(const float4*)Ap0;
    float4 a1 = *(const float4*)Ap1;
    float4 b0, b1;
    if (BT) {
        Bp0 = Bm + (size_t)(n0 + arow) * K + acol;
        Bp1 = Bp0 + (size_t)64 * K;
        b0 = *(const float4*)Bp0;
        b1 = *(const float4*)Bp1;
    } else {
        Bp0 = Bm + (size_t)brow * N + n0 + bcol;
        b0 = *(const float4*)Bp0;
        b1 = *(const float4*)(Bp0 + 4);
    }

    const int nchunk = K >> 4;
    for (int ch = 0; ch < nchunk; ch++) {
        // regs -> smem (A transposed to [k][m]; B to [k][n])
        As[acol + 0][arow]      = a0.x; As[acol + 1][arow]      = a0.y;
        As[acol + 2][arow]      = a0.z; As[acol + 3][arow]      = a0.w;
        As[acol + 0][arow + 64] = a1.x; As[acol + 1][arow + 64] = a1.y;
        As[acol + 2][arow + 64] = a1.z; As[acol + 3][arow + 64] = a1.w;
        if (BT) {
            Bs[acol + 0][arow]      = b0.x; Bs[acol + 1][arow]      = b0.y;
            Bs[acol + 2][arow]      = b0.z; Bs[acol + 3][arow]      = b0.w;
            Bs[acol + 0][arow + 64] = b1.x; Bs[acol + 1][arow + 64] = b1.y;
            Bs[acol + 2][arow + 64] = b1.z; Bs[acol + 3][arow + 64] = b1.w;
        } else {
            *(float4*)&Bs[brow][bcol]     = b0;
            *(float4*)&Bs[brow][bcol + 4] = b1;
        }
        __syncthreads();

        if (ch + 1 < nchunk) {             // prefetch next chunk into regs
            int ko = (ch + 1) << 4;
            a0 = *(const float4*)(Ap0 + ko);
            a1 = *(const float4*)(Ap1 + ko);
            if (BT) {
                b0 = *(const float4*)(Bp0 + ko);
                b1 = *(const float4*)(Bp1 + ko);
            } else {
                b0 = *(const float4*)(Bp0 + (size_t)ko * N);
                b1 = *(const float4*)(Bp0 + (size_t)ko * N + 4);
            }
        }

#pragma unroll
        for (int k = 0; k < 16; k++) {
            float4 xa0 = *(const float4*)&As[k][mf];
            float4 xa1 = *(const float4*)&As[k][mf + 4];
            float4 xb0 = *(const float4*)&Bs[k][nf];
            float4 xb1 = *(const float4*)&Bs[k][nf + 4];
            float am[8] = {xa0.x, xa0.y, xa0.z, xa0.w, xa1.x, xa1.y, xa1.z, xa1.w};
            float bn[8] = {xb0.x, xb0.y, xb0.z, xb0.w, xb1.x, xb1.y, xb1.z, xb1.w};
#pragma unroll
            for (int i = 0; i < 8; i++)
#pragma unroll
                for (int j = 0; j < 8; j++) acc[i][j] += am[i] * bn[j];
        }
        __syncthreads();
    }

    float bv[8];
#pragma unroll
    for (int j = 0; j < 8; j++) bv[j] = bias ? bias[n0 + nf + j] : 0.0f;
#pragma unroll
    for (int i = 0; i < 8; i++) {
        float v[8];
#pragma unroll
        for (int j = 0; j < 8; j++) {
            float t = acc[i][j] + bv[j];
            v[j] = RELU ? fmaxf(t, 0.0f) : t;
        }
        float* cp = C + (size_t)(m0 + mf + i) * N + n0 + nf;
        *(float4*)cp       = make_float4(v[0], v[1], v[2], v[3]);
        *(float4*)(cp + 4) = make_float4(v[4], v[5], v[6], v[7]);
    }
}

// ---------------- LSTM step: g = Gx[t] + h @ WhhP^T, fused gates ----------------
// grid (64, 4): 16 n'-cols (=4 hidden units) x 64 batch rows per CTA. 256 threads.
// RAW=1: used once to compute g_r = hN @ WhhP^T (no gates, no Gx).
#define LSTM_SMEM ((256*68 + 256*17 + 64*17 + 64*17) * 4)
template<int RAW>
__global__ void __launch_bounds__(256) lstm_step_k(int t)
{
    extern __shared__ float sm[];
    float* hs  = sm;                    // [256][68]  h tile transposed [k][b]
    float* ws  = sm + 256 * 68;         // [256][17]  Whh' tile [k][n'l]
    float* gts = ws + 256 * 17;         // [64][17]   Gx tile
    float* gsm = gts + 64 * 17;         // [64][17]   g exchange

    const int tid = threadIdx.x;
    const int b0  = blockIdx.y << 6;    // batch base
    const int np0 = blockIdx.x << 4;    // n' base (16 cols = 4 units)
    const float* __restrict__ hin = g_h[t & 1];

    // fill h tile (transpose): hs[k][r] = h[b0+r][k], k = tid
#pragma unroll 4
    for (int r = 0; r < 64; r++)
        hs[tid * 68 + r] = hin[(b0 + r) * H_ + tid];
    // fill W tile: ws[k][j] = WhhP[np0+j][k]
#pragma unroll
    for (int j = 0; j < 16; j++)
        ws[tid * 17 + j] = g_WhhP[(np0 + j) * H_ + tid];
    if (!RAW) {
        int gr = tid >> 2, gc = (tid & 3) << 2;
        float4 gv = *(const float4*)&g_Gx[((size_t)t * B_ + b0 + gr) * G4 + np0 + gc];
        gts[gr * 17 + gc + 0] = gv.x; gts[gr * 17 + gc + 1] = gv.y;
        gts[gr * 17 + gc + 2] = gv.z; gts[gr * 17 + gc + 3] = gv.w;
    }
    __syncthreads();

    const int b4 = tid & 15;   // batch quad index
    const int nl = tid >> 4;   // local n' 0..15
    float4 acc = make_float4(0.f, 0.f, 0.f, 0.f);
#pragma unroll 8
    for (int k = 0; k < H_; k++) {
        float4 a = *(const float4*)&hs[k * 68 + (b4 << 2)];
        float  w = ws[k * 17 + nl];
        acc.x += a.x * w; acc.y += a.y * w; acc.z += a.z * w; acc.w += a.w * w;
    }

    if (RAW) {
        int bb = b0 + (b4 << 2);
        g_r[(bb + 0) * G4 + np0 + nl] = acc.x;
        g_r[(bb + 1) * G4 + np0 + nl] = acc.y;
        g_r[(bb + 2) * G4 + np0 + nl] = acc.z;
        g_r[(bb + 3) * G4 + np0 + nl] = acc.w;
    } else {
        int rb = b4 << 2;
        gsm[(rb + 0) * 17 + nl] = acc.x + gts[(rb + 0) * 17 + nl];
        gsm[(rb + 1) * 17 + nl] = acc.y + gts[(rb + 1) * 17 + nl];
        gsm[(rb + 2) * 17 + nl] = acc.z + gts[(rb + 2) * 17 + nl];
        gsm[(rb + 3) * 17 + nl] = acc.w + gts[(rb + 3) * 17 + nl];
        __syncthreads();
        // gates: thread -> (batch-local bl, unit-local u)
        int bl = tid >> 2, u = tid & 3;
        float gi = gsm[bl * 17 + u * 4 + 0];
        float gf = gsm[bl * 17 + u * 4 + 1];
        float gg = gsm[bl * 17 + u * 4 + 2];
        float go = gsm[bl * 17 + u * 4 + 3];
        int ci = (b0 + bl) * H_ + (np0 >> 2) + u;
        float c = sigmf(gf) * g_c[ci] + sigmf(gi) * tanhf(gg);
        g_c[ci] = c;
        g_h[(t + 1) & 1][ci] = sigmf(go) * tanhf(c);
    }
}

// ---------------- tgt positions: parallel single LSTM step from (hN, cN) ----------------
__global__ void tgt_gates()
{
    int row = blockIdx.x;            // t*256 + b   (t = 0..99, actual s = t+100)
    int tt = row >> 8, b = row & 255;
    int j = threadIdx.x;             // hidden unit 0..255
    float4 gv = *(const float4*)&g_Gx[((size_t)(tt + T_) * B_ + b) * G4 + (j << 2)];
    float4 rv = *(const float4*)&g_r[b * G4 + (j << 2)];
    float gi = gv.x + rv.x, gf = gv.y + rv.y, gg = gv.z + rv.z, go = gv.w + rv.w;
    float c = sigmf(gf) * g_c[b * H_ + j] + sigmf(gi) * tanhf(gg);
    g_Hout[(size_t)row * H_ + j] = sigmf(go) * tanhf(c);
}

// ---------------- final: out = sigmoid(Z2 @ W3 + b3), remap (t,b) -> (b,t) ----------------
__global__ void final_dot(const float* __restrict__ W3, const float* __restrict__ b3,
                          float* __restrict__ out)
{
    int row  = blockIdx.x * 8 + (threadIdx.x >> 5);  // t*256+b
    int lane = threadIdx.x & 31;
    float4 z = *(const float4*)&g_Z2[row * P2_ + lane * 4];
    float4 w = *(const float4*)&W3[lane * 4];
    float s = z.x * w.x + z.y * w.y + z.z * w.z + z.w * w.w;
#pragma unroll
    for (int o = 16; o > 0; o >>= 1) s += __shfl_xor_sync(0xffffffffu, s, o);
    if (lane == 0) {
        int tt = row >> 8, b = row & 255;
        out[b * T_ + tt] = 1.0f / (1.0f + expf(-(s + b3[0])));
    }
}

// ---------------- launcher ----------------
extern "C" void kernel_launch(void* const* d_in, const int* in_sizes, int n_in,
                              void* d_out, int out_size)
{
    const int*   x    = (const int*)  d_in[0];
    const float* emb  = (const float*)d_in[1];
    const float* Wih  = (const float*)d_in[2];
    const float* Whh  = (const float*)d_in[3];
    const float* bih  = (const float*)d_in[4];
    const float* bhh  = (const float*)d_in[5];
    const float* W1   = (const float*)d_in[6];
    const float* b1   = (const float*)d_in[7];
    const float* W2   = (const float*)d_in[8];
    const float* b2   = (const float*)d_in[9];
    const float* W3   = (const float*)d_in[10];
    const float* b3   = (const float*)d_in[11];
    float* out = (float*)d_out;

    cudaFuncSetAttribute(lstm_step_k<0>, cudaFuncAttributeMaxDynamicSharedMemorySize, LSTM_SMEM);
    cudaFuncSetAttribute(lstm_step_k<1>, cudaFuncAttributeMaxDynamicSharedMemorySize, LSTM_SMEM);

    void *pe, *pGx, *pWihP, *pbias, *pHout, *pZ1, *pZ2;
    cudaGetSymbolAddress(&pe,    g_e);
    cudaGetSymbolAddress(&pGx,   g_Gx);
    cudaGetSymbolAddress(&pWihP, g_WihP);
    cudaGetSymbolAddress(&pbias, g_biasP);
    cudaGetSymbolAddress(&pHout, g_Hout);
    cudaGetSymbolAddress(&pZ1,   g_Z1);
    cudaGetSymbolAddress(&pZ2,   g_Z2);

    // prep
    permute_weights<<<G4, 256>>>(Wih, Whh, bih, bhh);
    zero_hc<<<(B_ * H_ + 255) / 256, 256>>>();
    embed_mean<<<B_ * S_, E_>>>(x, emb);

    // x-part for ALL 200 positions, biases folded in:
    // Gx[s*256+b][n'] = e[s][b] . WihP[n'] + biasP[n']
    gemm128<1, 0><<<dim3(G4 / 128, (S_ * B_) / 128), 256>>>(
        (const float*)pe, (const float*)pWihP, (const float*)pbias, (float*)pGx,
        S_ * B_, G4, E_);

    // sequential LSTM over hist (s = 0..99)
    for (int t = 0; t < T_; t++)
        lstm_step_k<0><<<dim3(64, 4), 256, LSTM_SMEM>>>(t);

    // r = hN @ WhhP^T  (hN lives in g_h[0] after 100 steps)
    lstm_step_k<1><<<dim3(64, 4), 256, LSTM_SMEM>>>(100);

    // parallel gates for the 100 tgt positions
    tgt_gates<<<T_ * B_, 256>>>();

    // MLP
    gemm128<0, 1><<<dim3(P1_ / 128, (T_ * B_) / 128), 256>>>(
        (const float*)pHout, W1, b1, (float*)pZ1, T_ * B_, P1_, H_);
    gemm128<0, 1><<<dim3(P2_ / 128, (T_ * B_) / 128), 256>>>(
        (const float*)pZ1, W2, b2, (float*)pZ2, T_ * B_, P1_ /*K*/ == P1_ ? P2_ : P2_, P1_);

    // head + layout remap to (B, T)
    final_dot<<<(T_ * B_) / 8, 256>>>(W3, b3, out);
}

// round 2
// speedup vs baseline: 1.5637x; 1.5637x over previous
#include <cuda_runtime.h>
#include <math.h>

// Problem dims
#define B_   256
#define S_   200
#define T_   100
#define F_   10
#define E_   128
#define H_   256
#define G4   1024   // 4*H
#define P1_  512
#define P2_  128

// persistent LSTM config
#define NCTA 128
#define NTHR 128
#define LSTM_SMEM_FLOATS (256*36 + 256*68)

// ---------------- scratch (device globals; no runtime alloc allowed) ----------------
__device__ float g_e   [S_*B_*E_];           // e transposed: [s][b][k]
__device__ float g_Gx  [(size_t)S_*B_*G4];   // x-part + biases, gate-interleaved [s][b][n']
__device__ float g_WihP[G4*E_];              // permuted rows: n' = 4*unit+gate
__device__ float g_WhhP[G4*H_];
__device__ float g_biasP[G4];
__device__ float g_hT[2][H_*B_];             // hidden state TRANSPOSED: [unit][b], ping-pong
__device__ float g_c[B_*H_];                 // final cN, layout [b][unit] (for tgt_gates)
__device__ float g_r[B_*G4];                 // hN @ WhhP^T, layout [b][n']
__device__ float g_Hout[T_*B_*H_];
__device__ float g_Z1[(size_t)T_*B_*P1_];
__device__ float g_Z2[T_*B_*P2_];

// grid barrier state (survives graph replays: cnt ends at 0, gen is monotonic)
__device__ int          g_cnt;
__device__ volatile int g_gen;

__device__ __forceinline__ float sigmf(float x) { return 1.0f / (1.0f + expf(-x)); }

// ---------------- small prep kernels ----------------
__global__ void permute_weights(const float* __restrict__ Wih, const float* __restrict__ Whh,
                                const float* __restrict__ bih, const float* __restrict__ bhh)
{
    int np  = blockIdx.x;                 // n' 0..1023
    int src = (np & 3) * H_ + (np >> 2);  // gate*256 + unit
    int t   = threadIdx.x;
    if (t < E_) g_WihP[np * E_ + t] = Wih[src * E_ + t];
    g_WhhP[np * H_ + t] = Whh[src * H_ + t];
    if (t == 0) g_biasP[np] = bih[src] + bhh[src];
}

__global__ void zero_h0()
{
    int i = blockIdx.x * 256 + threadIdx.x;
    if (i < B_ * H_) g_hT[0][i] = 0.0f;
}

__global__ void embed_mean(const int* __restrict__ x, const float* __restrict__ emb)
{
    int row = blockIdx.x;            // b*S_ + s
    int b = row / S_, s = row % S_;
    const int* xi = x + row * F_;
    int k = threadIdx.x;
    float sum = 0.0f;
#pragma unroll
    for (int f = 0; f < F_; f++) sum += emb[(size_t)xi[f] * E_ + k];
    g_e[((size_t)s * B_ + b) * E_ + k] = sum * (1.0f / (float)F_);
}

// ---------------- generic fp32 GEMM (unchanged from R1) ----------------
template<int BT, int RELU>
__global__ void __launch_bounds__(256) gemm128(const float* __restrict__ A,
                                               const float* __restrict__ Bm,
                                               const float* __restrict__ bias,
                                               float* __restrict__ C,
                                               int M, int N, int K)
{
    __shared__ float As[16][132];
    __shared__ float Bs[16][132];

    const int tid  = threadIdx.x;
    const int m0   = blockIdx.y << 7;
    const int n0   = blockIdx.x << 7;
    const int arow = tid >> 2, acol = (tid & 3) << 2;
    const int brow = tid >> 4, bcol = (tid & 15) << 3;
    const int mf   = (tid >> 4) << 3;
    const int nf   = (tid & 15) << 3;

    float acc[8][8];
#pragma unroll
    for (int i = 0; i < 8; i++)
#pragma unroll
        for (int j = 0; j < 8; j++) acc[i][j] = 0.0f;

    const float* Ap0 = A + (size_t)(m0 + arow) * K + acol;
    const float* Ap1 = Ap0 + (size_t)64 * K;
    const float* Bp0; const float* Bp1 = 0;
    float4 a0 = *(const float4*)Ap0;
    float4 a1 = *(const float4*)Ap1;
    float4 b0, b1;
    if (BT) {
        Bp0 = Bm + (size_t)(n0 + arow) * K + acol;
        Bp1 = Bp0 + (size_t)64 * K;
        b0 = *(const float4*)Bp0;
        b1 = *(const float4*)Bp1;
    } else {
        Bp0 = Bm + (size_t)brow * N + n0 + bcol;
        b0 = *(const float4*)Bp0;
        b1 = *(const float4*)(Bp0 + 4);
    }

    const int nchunk = K >> 4;
    for (int ch = 0; ch < nchunk; ch++) {
        As[acol + 0][arow]      = a0.x; As[acol + 1][arow]      = a0.y;
        As[acol + 2][arow]      = a0.z; As[acol + 3][arow]      = a0.w;
        As[acol + 0][arow + 64] = a1.x; As[acol + 1][arow + 64] = a1.y;
        As[acol + 2][arow + 64] = a1.z; As[acol + 3][arow + 64] = a1.w;
        if (BT) {
            Bs[acol + 0][arow]      = b0.x; Bs[acol + 1][arow]      = b0.y;
            Bs[acol + 2][arow]      = b0.z; Bs[acol + 3][arow]      = b0.w;
            Bs[acol + 0][arow + 64] = b1.x; Bs[acol + 1][arow + 64] = b1.y;
            Bs[acol + 2][arow + 64] = b1.z; Bs[acol + 3][arow + 64] = b1.w;
        } else {
            *(float4*)&Bs[brow][bcol]     = b0;
            *(float4*)&Bs[brow][bcol + 4] = b1;
        }
        __syncthreads();

        if (ch + 1 < nchunk) {
            int ko = (ch + 1) << 4;
            a0 = *(const float4*)(Ap0 + ko);
            a1 = *(const float4*)(Ap1 + ko);
            if (BT) {
                b0 = *(const float4*)(Bp0 + ko);
                b1 = *(const float4*)(Bp1 + ko);
            } else {
                b0 = *(const float4*)(Bp0 + (size_t)ko * N);
                b1 = *(const float4*)(Bp0 + (size_t)ko * N + 4);
            }
        }

#pragma unroll
        for (int k = 0; k < 16; k++) {
            float4 xa0 = *(const float4*)&As[k][mf];
            float4 xa1 = *(const float4*)&As[k][mf + 4];
            float4 xb0 = *(const float4*)&Bs[k][nf];
            float4 xb1 = *(const float4*)&Bs[k][nf + 4];
            float am[8] = {xa0.x, xa0.y, xa0.z, xa0.w, xa1.x, xa1.y, xa1.z, xa1.w};
            float bn[8] = {xb0.x, xb0.y, xb0.z, xb0.w, xb1.x, xb1.y, xb1.z, xb1.w};
#pragma unroll
            for (int i = 0; i < 8; i++)
#pragma unroll
                for (int j = 0; j < 8; j++) acc[i][j] += am[i] * bn[j];
        }
        __syncthreads();
    }

    float bv[8];
#pragma unroll
    for (int j = 0; j < 8; j++) bv[j] = bias ? bias[n0 + nf + j] : 0.0f;
#pragma unroll
    for (int i = 0; i < 8; i++) {
        float v[8];
#pragma unroll
        for (int j = 0; j < 8; j++) {
            float t = acc[i][j] + bv[j];
            v[j] = RELU ? fmaxf(t, 0.0f) : t;
        }
        float* cp = C + (size_t)(m0 + mf + i) * N + n0 + nf;
        *(float4*)cp       = make_float4(v[0], v[1], v[2], v[3]);
        *(float4*)(cp + 4) = make_float4(v[4], v[5], v[6], v[7]);
    }
}

// ---------------- persistent LSTM: all 100 steps + r = hN@W in ONE kernel ----------------
// 128 CTAs x 128 threads, all co-resident (106KB smem/CTA -> 1 CTA/SM, 128 <= 148 SMs).
// CTA tile: 64 batch x 32 n' (= 8 hidden units). W tile resident in smem for whole kernel.
// Thread: 4 consecutive b x 4 gates of ONE unit -> c lives in registers for all steps.
// h stored transposed hT[unit][b] -> coalesced store and coalesced next-step load.
// Cross-CTA data (hT) read with __ldcg (L2) since L1s are not coherent.
__global__ void __launch_bounds__(NTHR, 1) lstm_persist()
{
    extern __shared__ float sm[];
    float* ws = sm;               // [256 k][36 pad] W tile (resident)
    float* hs = sm + 256 * 36;    // [256 k][68 pad] h tile (per step)

    const int tid = threadIdx.x;
    const int cta = blockIdx.x;
    const int b0  = (cta & 3) << 6;    // batch base (4 tiles)
    const int np0 = (cta >> 2) << 5;   // n' base (32 tiles)
    const int bq  = tid & 15;          // batch quad 0..15
    const int nq  = tid >> 4;          // unit-in-tile 0..7
    const int u   = (np0 >> 2) + nq;   // global hidden unit
    const int bb  = b0 + (bq << 2);    // this thread's first batch row

    // Load W tile once (resident across all 100 steps)
    for (int idx = tid; idx < 32 * 256; idx += NTHR) {
        int j = idx >> 8, k = idx & 255;
        ws[k * 36 + j] = g_WhhP[(np0 + j) * H_ + k];
    }

    float c[4] = {0.f, 0.f, 0.f, 0.f};   // cell state in registers, all steps

    for (int s = 0; s <= T_; s++) {
        // prefetch this thread's Gx tile (4 x float4) from DRAM
        float4 gx[4];
        if (s < T_) {
            const float* gp = g_Gx + ((size_t)s * B_ + bb) * G4 + np0 + (nq << 2);
#pragma unroll
            for (int i = 0; i < 4; i++)
                gx[i] = __ldcg((const float4*)(gp + (size_t)i * G4));
        }

        // load h tile [256 k][64 b] from hT[s&1] (L2 only!)
        const float* hp = g_hT[s & 1];
#pragma unroll
        for (int it = 0; it < 32; it++) {
            int i  = tid + it * NTHR;          // 0..4095 float4 slots
            int k  = i >> 4;
            int bl = (i & 15) << 2;
            float4 v = __ldcg((const float4*)&hp[k * B_ + b0 + bl]);
            *(float4*)&hs[k * 68 + bl] = v;
        }
        __syncthreads();

        float a[4][4];
#pragma unroll
        for (int i = 0; i < 4; i++)
#pragma unroll
            for (int j = 0; j < 4; j++) a[i][j] = 0.f;

#pragma unroll 8
        for (int k = 0; k < H_; k++) {
            float4 hv = *(const float4*)&hs[k * 68 + (bq << 2)];
            float4 wv = *(const float4*)&ws[k * 36 + (nq << 2)];
            a[0][0] += hv.x * wv.x; a[0][1] += hv.x * wv.y; a[0][2] += hv.x * wv.z; a[0][3] += hv.x * wv.w;
            a[1][0] += hv.y * wv.x; a[1][1] += hv.y * wv.y; a[1][2] += hv.y * wv.z; a[1][3] += hv.y * wv.w;
            a[2][0] += hv.z * wv.x; a[2][1] += hv.z * wv.y; a[2][2] += hv.z * wv.z; a[2][3] += hv.z * wv.w;
            a[3][0] += hv.w * wv.x; a[3][1] += hv.w * wv.y; a[3][2] += hv.w * wv.z; a[3][3] += hv.w * wv.w;
        }

        if (s < T_) {
            float hv4[4];
#pragma unroll
            for (int i = 0; i < 4; i++) {
                float gi = a[i][0] + gx[i].x;
                float gf = a[i][1] + gx[i].y;
                float gg = a[i][2] + gx[i].z;
                float go = a[i][3] + gx[i].w;
                c[i] = sigmf(gf) * c[i] + sigmf(gi) * tanhf(gg);
                hv4[i] = sigmf(go) * tanhf(c[i]);
            }
            *(float4*)&g_hT[(s + 1) & 1][u * B_ + bb] =
                make_float4(hv4[0], hv4[1], hv4[2], hv4[3]);

            // ---- grid barrier (release-acquire via L2 atomics) ----
            __threadfence();
            __syncthreads();
            if (tid == 0) {
                int snap = g_gen;                       // volatile read
                int old  = atomicAdd(&g_cnt, 1);
                if (old == NCTA - 1) {
                    g_cnt = 0;
                    __threadfence();
                    g_gen = snap + 1;
                } else {
                    while (g_gen == snap) { __nanosleep(40); }
                    __threadfence();
                }
            }
            __syncthreads();
        } else {
            // s == 100: r = hN @ WhhP^T and export cN (one-time scattered writes)
#pragma unroll
            for (int i = 0; i < 4; i++) {
                *(float4*)&g_r[(size_t)(bb + i) * G4 + np0 + (nq << 2)] =
                    make_float4(a[i][0], a[i][1], a[i][2], a[i][3]);
                g_c[(bb + i) * H_ + u] = c[i];
            }
        }
    }
}

// ---------------- tgt positions: parallel single LSTM step from (hN, cN) ----------------
__global__ void tgt_gates()
{
    int row = blockIdx.x;            // t*256 + b
    int tt = row >> 8, b = row & 255;
    int j = threadIdx.x;             // hidden unit
    float4 gv = *(const float4*)&g_Gx[((size_t)(tt + T_) * B_ + b) * G4 + (j << 2)];
    float4 rv = *(const float4*)&g_r[b * G4 + (j << 2)];
    float gi = gv.x + rv.x, gf = gv.y + rv.y, gg = gv.z + rv.z, go = gv.w + rv.w;
    float c = sigmf(gf) * g_c[b * H_ + j] + sigmf(gi) * tanhf(gg);
    g_Hout[(size_t)row * H_ + j] = sigmf(go) * tanhf(c);
}

// ---------------- final: out = sigmoid(Z2 @ W3 + b3), remap (t,b) -> (b,t) ----------------
__global__ void final_dot(const float* __restrict__ W3, const float* __restrict__ b3,
                          float* __restrict__ out)
{
    int row  = blockIdx.x * 8 + (threadIdx.x >> 5);
    int lane = threadIdx.x & 31;
    float4 z = *(const float4*)&g_Z2[row * P2_ + lane * 4];
    float4 w = *(const float4*)&W3[lane * 4];
    float s = z.x * w.x + z.y * w.y + z.z * w.z + z.w * w.w;
#pragma unroll
    for (int o = 16; o > 0; o >>= 1) s += __shfl_xor_sync(0xffffffffu, s, o);
    if (lane == 0) {
        int tt = row >> 8, b = row & 255;
        out[b * T_ + tt] = 1.0f / (1.0f + expf(-(s + b3[0])));
    }
}

// ---------------- launcher ----------------
extern "C" void kernel_launch(void* const* d_in, const int* in_sizes, int n_in,
                              void* d_out, int out_size)
{
    const int*   x    = (const int*)  d_in[0];
    const float* emb  = (const float*)d_in[1];
    const float* Wih  = (const float*)d_in[2];
    const float* Whh  = (const float*)d_in[3];
    const float* bih  = (const float*)d_in[4];
    const float* bhh  = (const float*)d_in[5];
    const float* W1   = (const float*)d_in[6];
    const float* b1   = (const float*)d_in[7];
    const float* W2   = (const float*)d_in[8];
    const float* b2   = (const float*)d_in[9];
    const float* W3   = (const float*)d_in[10];
    const float* b3   = (const float*)d_in[11];
    float* out = (float*)d_out;

    cudaFuncSetAttribute(lstm_persist, cudaFuncAttributeMaxDynamicSharedMemorySize,
                         LSTM_SMEM_FLOATS * 4);

    void *pe, *pGx, *pWihP, *pbias, *pHout, *pZ1, *pZ2;
    cudaGetSymbolAddress(&pe,    g_e);
    cudaGetSymbolAddress(&pGx,   g_Gx);
    cudaGetSymbolAddress(&pWihP, g_WihP);
    cudaGetSymbolAddress(&pbias, g_biasP);
    cudaGetSymbolAddress(&pHout, g_Hout);
    cudaGetSymbolAddress(&pZ1,   g_Z1);
    cudaGetSymbolAddress(&pZ2,   g_Z2);

    // prep
    permute_weights<<<G4, 256>>>(Wih, Whh, bih, bhh);
    zero_h0<<<(B_ * H_ + 255) / 256, 256>>>();
    embed_mean<<<B_ * S_, E_>>>(x, emb);

    // x-part for all 200 positions, biases folded in
    gemm128<1, 0><<<dim3(G4 / 128, (S_ * B_) / 128), 256>>>(
        (const float*)pe, (const float*)pWihP, (const float*)pbias, (float*)pGx,
        S_ * B_, G4, E_);

    // ALL 100 LSTM steps + r = hN@W in one persistent kernel
    lstm_persist<<<NCTA, NTHR, LSTM_SMEM_FLOATS * 4>>>();

    // parallel gates for the 100 tgt positions
    tgt_gates<<<T_ * B_, 256>>>();

    // MLP
    gemm128<0, 1><<<dim3(P1_ / 128, (T_ * B_) / 128), 256>>>(
        (const float*)pHout, W1, b1, (float*)pZ1, T_ * B_, P1_, H_);
    gemm128<0, 1><<<dim3(P2_ / 128, (T_ * B_) / 128), 256>>>(
        (const float*)pZ1, W2, b2, (float*)pZ2, T_ * B_, P2_, P1_);

    // head + layout remap to (B, T)
    final_dot<<<(T_ * B_) / 8, 256>>>(W3, b3, out);
}

// round 3
// speedup vs baseline: 2.0265x; 1.2960x over previous
#include <cuda_runtime.h>
#include <math.h>
#include <stdint.h>

// Problem dims
#define B_   256
#define S_   200
#define T_   100
#define F_   10
#define E_   128
#define H_   256
#define G4   1024   // 4*H
#define P1_  512
#define P2_  128

// persistent LSTM config
#define NCTA 128
#define NTHR 128
#define LSTM_SMEM_FLOATS (256*36 + 256*68)

// ---------------- scratch (device globals; no runtime alloc allowed) ----------------
__device__ float g_e   [S_*B_*E_];           // e transposed: [s][b][k]
__device__ float g_Gx  [(size_t)S_*B_*G4];   // x-part + biases, gate-interleaved [s][b][n']
__device__ float g_WihP[G4*E_];              // permuted rows: n' = 4*unit+gate
__device__ float g_WhhP[G4*H_];
__device__ float g_biasP[G4];
__device__ float g_hT[2][H_*B_];             // hidden state TRANSPOSED: [unit][b], ping-pong
__device__ float g_c[B_*H_];                 // final cN, layout [b][unit]
__device__ float g_r[B_*G4];                 // hN @ WhhP^T, layout [b][n']
__device__ float g_Hout[T_*B_*H_];
__device__ float g_Z1[(size_t)T_*B_*P1_];
__device__ float g_Z2[T_*B_*P2_];

// grid barrier state (survives graph replays: cnt ends at 0, gen is monotonic)
__device__ int          g_cnt;
__device__ volatile int g_gen;

__device__ __forceinline__ float sigmf(float x) { return 1.0f / (1.0f + expf(-x)); }

__device__ __forceinline__ uint32_t f2tf32(float f)
{
    uint32_t u;
    asm("cvt.rna.tf32.f32 %0, %1;" : "=r"(u) : "f"(f));
    return u;
}

__device__ __forceinline__ void mma_tf32(float* d, const uint32_t* a, const uint32_t* b)
{
    asm volatile(
        "mma.sync.aligned.m16n8k8.row.col.f32.tf32.tf32.f32 "
        "{%0,%1,%2,%3}, {%4,%5,%6,%7}, {%8,%9}, {%0,%1,%2,%3};\n"
        : "+f"(d[0]), "+f"(d[1]), "+f"(d[2]), "+f"(d[3])
        : "r"(a[0]), "r"(a[1]), "r"(a[2]), "r"(a[3]), "r"(b[0]), "r"(b[1]));
}

// ---------------- small prep kernels ----------------
__global__ void permute_weights(const float* __restrict__ Wih, const float* __restrict__ Whh,
                                const float* __restrict__ bih, const float* __restrict__ bhh)
{
    int np  = blockIdx.x;                 // n' 0..1023
    int src = (np & 3) * H_ + (np >> 2);  // gate*256 + unit
    int t   = threadIdx.x;
    if (t < E_) g_WihP[np * E_ + t] = Wih[src * E_ + t];
    g_WhhP[np * H_ + t] = Whh[src * H_ + t];
    if (t == 0) g_biasP[np] = bih[src] + bhh[src];
}

__global__ void zero_h0()
{
    int i = blockIdx.x * 256 + threadIdx.x;
    if (i < B_ * H_) g_hT[0][i] = 0.0f;
}

__global__ void embed_mean(const int* __restrict__ x, const float* __restrict__ emb)
{
    int row = blockIdx.x;            // b*S_ + s
    int b = row / S_, s = row % S_;
    const int* xi = x + row * F_;
    int k = threadIdx.x;
    float sum = 0.0f;
#pragma unroll
    for (int f = 0; f < F_; f++) sum += emb[(size_t)xi[f] * E_ + k];
    g_e[((size_t)s * B_ + b) * E_ + k] = sum * (1.0f / (float)F_);
}

// ---------------- tf32 tensor-core GEMM: C = act(A @ op(B) + bias) ----------------
// BT=1 : B given as (N,K) row-major, C = A·B^T ;  BT=0 : B given as (K,N) row-major.
// CTA tile 128x128, K-chunk 16, 256 threads = 8 warps (2m x 4n), warp tile 64x32.
// smem layout [k][m]/[k][n], pad 136 (8 mod 32) -> conflict-free fragment loads.
// Requires M%128==0, N%128==0, K%16==0.
template<int BT, int RELU>
__global__ void __launch_bounds__(256) gemm_tf32(const float* __restrict__ A,
                                                 const float* __restrict__ Bm,
                                                 const float* __restrict__ bias,
                                                 float* __restrict__ C,
                                                 int M, int N, int K)
{
    __shared__ uint32_t As[16][136];
    __shared__ uint32_t Bs[16][136];

    const int tid  = threadIdx.x;
    const int lane = tid & 31;
    const int warp = tid >> 5;
    const int g    = lane >> 2;        // group id (0..7)
    const int q    = lane & 3;         // thread-in-group (0..3)
    const int wm0  = (warp >> 2) << 6; // warp m base (0 or 64)
    const int wn0  = (warp & 3) << 5;  // warp n base (0,32,64,96)

    const int m0   = blockIdx.y << 7;
    const int n0   = blockIdx.x << 7;
    const int arow = tid >> 2, acol = (tid & 3) << 2;   // 128x16 loader
    const int brow = tid >> 4, bcol = (tid & 15) << 3;  // 16x128 loader (KN case)

    float acc[4][4][4];
#pragma unroll
    for (int mi = 0; mi < 4; mi++)
#pragma unroll
        for (int ni = 0; ni < 4; ni++)
#pragma unroll
            for (int r = 0; r < 4; r++) acc[mi][ni][r] = 0.0f;

    const float* Ap0 = A + (size_t)(m0 + arow) * K + acol;
    const float* Ap1 = Ap0 + (size_t)64 * K;
    const float* Bp0; const float* Bp1 = 0;
    float4 a0 = *(const float4*)Ap0;
    float4 a1 = *(const float4*)Ap1;
    float4 b0, b1;
    if (BT) {
        Bp0 = Bm + (size_t)(n0 + arow) * K + acol;
        Bp1 = Bp0 + (size_t)64 * K;
        b0 = *(const float4*)Bp0;
        b1 = *(const float4*)Bp1;
    } else {
        Bp0 = Bm + (size_t)brow * N + n0 + bcol;
        b0 = *(const float4*)Bp0;
        b1 = *(const float4*)(Bp0 + 4);
    }

    const int nchunk = K >> 4;
    for (int ch = 0; ch < nchunk; ch++) {
        // regs -> smem with tf32 conversion (A transposed to [k][m]; B to [k][n])
        As[acol + 0][arow]      = f2tf32(a0.x); As[acol + 1][arow]      = f2tf32(a0.y);
        As[acol + 2][arow]      = f2tf32(a0.z); As[acol + 3][arow]      = f2tf32(a0.w);
        As[acol + 0][arow + 64] = f2tf32(a1.x); As[acol + 1][arow + 64] = f2tf32(a1.y);
        As[acol + 2][arow + 64] = f2tf32(a1.z); As[acol + 3][arow + 64] = f2tf32(a1.w);
        if (BT) {
            Bs[acol + 0][arow]      = f2tf32(b0.x); Bs[acol + 1][arow]      = f2tf32(b0.y);
            Bs[acol + 2][arow]      = f2tf32(b0.z); Bs[acol + 3][arow]      = f2tf32(b0.w);
            Bs[acol + 0][arow + 64] = f2tf32(b1.x); Bs[acol + 1][arow + 64] = f2tf32(b1.y);
            Bs[acol + 2][arow + 64] = f2tf32(b1.z); Bs[acol + 3][arow + 64] = f2tf32(b1.w);
        } else {
            uint4 u0 = make_uint4(f2tf32(b0.x), f2tf32(b0.y), f2tf32(b0.z), f2tf32(b0.w));
            uint4 u1 = make_uint4(f2tf32(b1.x), f2tf32(b1.y), f2tf32(b1.z), f2tf32(b1.w));
            *(uint4*)&Bs[brow][bcol]     = u0;
            *(uint4*)&Bs[brow][bcol + 4] = u1;
        }
        __syncthreads();

        if (ch + 1 < nchunk) {             // prefetch next chunk into regs
            int ko = (ch + 1) << 4;
            a0 = *(const float4*)(Ap0 + ko);
            a1 = *(const float4*)(Ap1 + ko);
            if (BT) {
                b0 = *(const float4*)(Bp0 + ko);
                b1 = *(const float4*)(Bp1 + ko);
            } else {
                b0 = *(const float4*)(Bp0 + (size_t)ko * N);
                b1 = *(const float4*)(Bp0 + (size_t)ko * N + 4);
            }
        }

        // two k8 MMA steps per 16-chunk
#pragma unroll
        for (int ks = 0; ks < 2; ks++) {
            const int kr = ks * 8 + q;
            uint32_t af[4][4], bf[4][2];
#pragma unroll
            for (int mi = 0; mi < 4; mi++) {
                int m = wm0 + mi * 16 + g;
                af[mi][0] = As[kr][m];
                af[mi][1] = As[kr][m + 8];
                af[mi][2] = As[kr + 4][m];
                af[mi][3] = As[kr + 4][m + 8];
            }
#pragma unroll
            for (int ni = 0; ni < 4; ni++) {
                int n = wn0 + ni * 8 + g;
                bf[ni][0] = Bs[kr][n];
                bf[ni][1] = Bs[kr + 4][n];
            }
#pragma unroll
            for (int mi = 0; mi < 4; mi++)
#pragma unroll
                for (int ni = 0; ni < 4; ni++)
                    mma_tf32(acc[mi][ni], af[mi], bf[ni]);
        }
        __syncthreads();
    }

    // epilogue: bias + optional relu, float2 stores
#pragma unroll
    for (int ni = 0; ni < 4; ni++) {
        int cn = n0 + wn0 + ni * 8 + 2 * q;
        float bb0 = bias ? bias[cn]     : 0.0f;
        float bb1 = bias ? bias[cn + 1] : 0.0f;
#pragma unroll
        for (int mi = 0; mi < 4; mi++) {
            int r0 = m0 + wm0 + mi * 16 + g;
            float v0 = acc[mi][ni][0] + bb0;
            float v1 = acc[mi][ni][1] + bb1;
            float v2 = acc[mi][ni][2] + bb0;
            float v3 = acc[mi][ni][3] + bb1;
            if (RELU) {
                v0 = fmaxf(v0, 0.f); v1 = fmaxf(v1, 0.f);
                v2 = fmaxf(v2, 0.f); v3 = fmaxf(v3, 0.f);
            }
            *(float2*)&C[(size_t)r0 * N + cn]       = make_float2(v0, v1);
            *(float2*)&C[(size_t)(r0 + 8) * N + cn] = make_float2(v2, v3);
        }
    }
}

// ---------------- persistent LSTM: all 100 steps + r = hN@W in ONE kernel ----------------
__global__ void __launch_bounds__(NTHR, 1) lstm_persist()
{
    extern __shared__ float sm[];
    float* ws = sm;               // [256 k][36 pad] W tile (resident)
    float* hs = sm + 256 * 36;    // [256 k][68 pad] h tile (per step)

    const int tid = threadIdx.x;
    const int cta = blockIdx.x;
    const int b0  = (cta & 3) << 6;    // batch base
    const int np0 = (cta >> 2) << 5;   // n' base (32 cols = 8 units)
    const int bq  = tid & 15;
    const int nq  = tid >> 4;
    const int u   = (np0 >> 2) + nq;
    const int bb  = b0 + (bq << 2);

    for (int idx = tid; idx < 32 * 256; idx += NTHR) {
        int j = idx >> 8, k = idx & 255;
        ws[k * 36 + j] = g_WhhP[(np0 + j) * H_ + k];
    }

    float c[4] = {0.f, 0.f, 0.f, 0.f};

    for (int s = 0; s <= T_; s++) {
        float4 gx[4];
        if (s < T_) {
            const float* gp = g_Gx + ((size_t)s * B_ + bb) * G4 + np0 + (nq << 2);
#pragma unroll
            for (int i = 0; i < 4; i++)
                gx[i] = __ldcg((const float4*)(gp + (size_t)i * G4));
        }

        const float* hp = g_hT[s & 1];
#pragma unroll
        for (int it = 0; it < 32; it++) {
            int i  = tid + it * NTHR;
            int k  = i >> 4;
            int bl = (i & 15) << 2;
            float4 v = __ldcg((const float4*)&hp[k * B_ + b0 + bl]);
            *(float4*)&hs[k * 68 + bl] = v;
        }
        __syncthreads();

        float a[4][4];
#pragma unroll
        for (int i = 0; i < 4; i++)
#pragma unroll
            for (int j = 0; j < 4; j++) a[i][j] = 0.f;

#pragma unroll 8
        for (int k = 0; k < H_; k++) {
            float4 hv = *(const float4*)&hs[k * 68 + (bq << 2)];
            float4 wv = *(const float4*)&ws[k * 36 + (nq << 2)];
            a[0][0] += hv.x * wv.x; a[0][1] += hv.x * wv.y; a[0][2] += hv.x * wv.z; a[0][3] += hv.x * wv.w;
            a[1][0] += hv.y * wv.x; a[1][1] += hv.y * wv.y; a[1][2] += hv.y * wv.z; a[1][3] += hv.y * wv.w;
            a[2][0] += hv.z * wv.x; a[2][1] += hv.z * wv.y; a[2][2] += hv.z * wv.z; a[2][3] += hv.z * wv.w;
            a[3][0] += hv.w * wv.x; a[3][1] += hv.w * wv.y; a[3][2] += hv.w * wv.z; a[3][3] += hv.w * wv.w;
        }

        if (s < T_) {
            float hv4[4];
#pragma unroll
            for (int i = 0; i < 4; i++) {
                float gi = a[i][0] + gx[i].x;
                float gf = a[i][1] + gx[i].y;
                float gg = a[i][2] + gx[i].z;
                float go = a[i][3] + gx[i].w;
                c[i] = sigmf(gf) * c[i] + sigmf(gi) * tanhf(gg);
                hv4[i] = sigmf(go) * tanhf(c[i]);
            }
            *(float4*)&g_hT[(s + 1) & 1][u * B_ + bb] =
                make_float4(hv4[0], hv4[1], hv4[2], hv4[3]);

            __threadfence();
            __syncthreads();
            if (tid == 0) {
                int snap = g_gen;
                int old  = atomicAdd(&g_cnt, 1);
                if (old == NCTA - 1) {
                    g_cnt = 0;
                    __threadfence();
                    g_gen = snap + 1;
                } else {
                    while (g_gen == snap) { __nanosleep(40); }
                    __threadfence();
                }
            }
            __syncthreads();
        } else {
#pragma unroll
            for (int i = 0; i < 4; i++) {
                *(float4*)&g_r[(size_t)(bb + i) * G4 + np0 + (nq << 2)] =
                    make_float4(a[i][0], a[i][1], a[i][2], a[i][3]);
                g_c[(bb + i) * H_ + u] = c[i];
            }
        }
    }
}

// ---------------- tgt positions: parallel single LSTM step from (hN, cN) ----------------
__global__ void tgt_gates()
{
    int row = blockIdx.x;            // t*256 + b
    int tt = row >> 8, b = row & 255;
    int j = threadIdx.x;
    float4 gv = *(const float4*)&g_Gx[((size_t)(tt + T_) * B_ + b) * G4 + (j << 2)];
    float4 rv = *(const float4*)&g_r[b * G4 + (j << 2)];
    float gi = gv.x + rv.x, gf = gv.y + rv.y, gg = gv.z + rv.z, go = gv.w + rv.w;
    float c = sigmf(gf) * g_c[b * H_ + j] + sigmf(gi) * tanhf(gg);
    g_Hout[(size_t)row * H_ + j] = sigmf(go) * tanhf(c);
}

// ---------------- final: out = sigmoid(Z2 @ W3 + b3), remap (t,b) -> (b,t) ----------------
__global__ void final_dot(const float* __restrict__ W3, const float* __restrict__ b3,
                          float* __restrict__ out)
{
    int row  = blockIdx.x * 8 + (threadIdx.x >> 5);
    int lane = threadIdx.x & 31;
    float4 z = *(const float4*)&g_Z2[row * P2_ + lane * 4];
    float4 w = *(const float4*)&W3[lane * 4];
    float s = z.x * w.x + z.y * w.y + z.z * w.z + z.w * w.w;
#pragma unroll
    for (int o = 16; o > 0; o >>= 1) s += __shfl_xor_sync(0xffffffffu, s, o);
    if (lane == 0) {
        int tt = row >> 8, b = row & 255;
        out[b * T_ + tt] = 1.0f / (1.0f + expf(-(s + b3[0])));
    }
}

// ---------------- launcher ----------------
extern "C" void kernel_launch(void* const* d_in, const int* in_sizes, int n_in,
                              void* d_out, int out_size)
{
    const int*   x    = (const int*)  d_in[0];
    const float* emb  = (const float*)d_in[1];
    const float* Wih  = (const float*)d_in[2];
    const float* Whh  = (const float*)d_in[3];
    const float* bih  = (const float*)d_in[4];
    const float* bhh  = (const float*)d_in[5];
    const float* W1   = (const float*)d_in[6];
    const float* b1   = (const float*)d_in[7];
    const float* W2   = (const float*)d_in[8];
    const float* b2   = (const float*)d_in[9];
    const float* W3   = (const float*)d_in[10];
    const float* b3   = (const float*)d_in[11];
    float* out = (float*)d_out;

    cudaFuncSetAttribute(lstm_persist, cudaFuncAttributeMaxDynamicSharedMemorySize,
                         LSTM_SMEM_FLOATS * 4);

    void *pe, *pGx, *pWihP, *pbias, *pHout, *pZ1, *pZ2;
    cudaGetSymbolAddress(&pe,    g_e);
    cudaGetSymbolAddress(&pGx,   g_Gx);
    cudaGetSymbolAddress(&pWihP, g_WihP);
    cudaGetSymbolAddress(&pbias, g_biasP);
    cudaGetSymbolAddress(&pHout, g_Hout);
    cudaGetSymbolAddress(&pZ1,   g_Z1);
    cudaGetSymbolAddress(&pZ2,   g_Z2);

    // prep
    permute_weights<<<G4, 256>>>(Wih, Whh, bih, bhh);
    zero_h0<<<(B_ * H_ + 255) / 256, 256>>>();
    embed_mean<<<B_ * S_, E_>>>(x, emb);

    // x-part for all 200 positions (tensor cores), biases folded in
    gemm_tf32<1, 0><<<dim3(G4 / 128, (S_ * B_) / 128), 256>>>(
        (const float*)pe, (const float*)pWihP, (const float*)pbias, (float*)pGx,
        S_ * B_, G4, E_);

    // ALL 100 LSTM steps + r = hN@W in one persistent kernel
    lstm_persist<<<NCTA, NTHR, LSTM_SMEM_FLOATS * 4>>>();

    // parallel gates for the 100 tgt positions
    tgt_gates<<<T_ * B_, 256>>>();

    // MLP (tensor cores)
    gemm_tf32<0, 1><<<dim3(P1_ / 128, (T_ * B_) / 128), 256>>>(
        (const float*)pHout, W1, b1, (float*)pZ1, T_ * B_, P1_, H_);
    gemm_tf32<0, 1><<<dim3(P2_ / 128, (T_ * B_) / 128), 256>>>(
        (const float*)pZ1, W2, b2, (float*)pZ2, T_ * B_, P2_, P1_);

    // head + layout remap to (B, T)
    final_dot<<<(T_ * B_) / 8, 256>>>(W3, b3, out);
}

// round 4
// speedup vs baseline: 2.8655x; 1.4140x over previous
#include <cuda_runtime.h>
#include <cuda_fp16.h>
#include <math.h>
#include <stdint.h>

// Problem dims
#define B_   256
#define S_   200
#define T_   100
#define F_   10
#define E_   128
#define H_   256
#define G4   1024   // 4*H
#define P1_  512
#define P2_  128

// ---------------- scratch (device globals; no runtime alloc allowed) ----------------
__device__ float  g_e   [S_*B_*E_];           // e transposed: [s][b][k]
__device__ float  g_Gx  [(size_t)S_*B_*G4];   // x-part + biases, gate-interleaved [s][b][n']
__device__ float  g_WihP[G4*E_];              // permuted rows: n' = 4*unit+gate
__device__ float  g_WhhP[G4*H_];
__device__ float  g_biasP[G4];
__device__ __half g_hF[2][B_*H_];             // hidden state fp16 [b][u], ping-pong
__device__ float  g_c[B_*H_];                 // final cN, layout [b][unit]
__device__ float  g_r[B_*G4];                 // hN @ WhhP^T, layout [b][n']
__device__ float  g_Hout[T_*B_*H_];
__device__ float  g_Z1[(size_t)T_*B_*P1_];
__device__ float  g_Z2[T_*B_*P2_];

// per-batch-group barrier state (4 independent groups of 32 CTAs)
__device__ int          g_cnt4[4];
__device__ volatile int g_gen4[4];

__device__ __forceinline__ float sigmf(float x) { return 1.0f / (1.0f + expf(-x)); }

__device__ __forceinline__ uint32_t f2tf32(float f)
{
    uint32_t u;
    asm("cvt.rna.tf32.f32 %0, %1;" : "=r"(u) : "f"(f));
    return u;
}

__device__ __forceinline__ void mma_tf32(float* d, const uint32_t* a, const uint32_t* b)
{
    asm volatile(
        "mma.sync.aligned.m16n8k8.row.col.f32.tf32.tf32.f32 "
        "{%0,%1,%2,%3}, {%4,%5,%6,%7}, {%8,%9}, {%0,%1,%2,%3};\n"
        : "+f"(d[0]), "+f"(d[1]), "+f"(d[2]), "+f"(d[3])
        : "r"(a[0]), "r"(a[1]), "r"(a[2]), "r"(a[3]), "r"(b[0]), "r"(b[1]));
}

__device__ __forceinline__ void mma_f16(float* d, const uint32_t* a, const uint32_t* b)
{
    asm volatile(
        "mma.sync.aligned.m16n8k16.row.col.f32.f16.f16.f32 "
        "{%0,%1,%2,%3}, {%4,%5,%6,%7}, {%8,%9}, {%0,%1,%2,%3};\n"
        : "+f"(d[0]), "+f"(d[1]), "+f"(d[2]), "+f"(d[3])
        : "r"(a[0]), "r"(a[1]), "r"(a[2]), "r"(a[3]), "r"(b[0]), "r"(b[1]));
}

__device__ __forceinline__ void ldmx4(uint32_t* r, uint32_t addr)
{
    asm volatile(
        "ldmatrix.sync.aligned.m8n8.x4.shared.b16 {%0,%1,%2,%3}, [%4];\n"
        : "=r"(r[0]), "=r"(r[1]), "=r"(r[2]), "=r"(r[3]) : "r"(addr));
}

__device__ __forceinline__ uint32_t packh2(float lo, float hi)
{
    __half2 h = __floats2half2_rn(lo, hi);
    return *reinterpret_cast<uint32_t*>(&h);
}

// ---------------- small prep kernels ----------------
__global__ void permute_weights(const float* __restrict__ Wih, const float* __restrict__ Whh,
                                const float* __restrict__ bih, const float* __restrict__ bhh)
{
    int np  = blockIdx.x;                 // n' 0..1023
    int src = (np & 3) * H_ + (np >> 2);  // gate*256 + unit
    int t   = threadIdx.x;
    if (t < E_) g_WihP[np * E_ + t] = Wih[src * E_ + t];
    g_WhhP[np * H_ + t] = Whh[src * H_ + t];
    if (t == 0) g_biasP[np] = bih[src] + bhh[src];
}

__global__ void zero_h0()
{
    int i = blockIdx.x * 256 + threadIdx.x;
    if (i < (B_ * H_) / 2) ((uint32_t*)g_hF[0])[i] = 0;
}

__global__ void embed_mean(const int* __restrict__ x, const float* __restrict__ emb)
{
    int row = blockIdx.x;            // b*S_ + s
    int b = row / S_, s = row % S_;
    const int* xi = x + row * F_;
    int k = threadIdx.x;
    float sum = 0.0f;
#pragma unroll
    for (int f = 0; f < F_; f++) sum += emb[(size_t)xi[f] * E_ + k];
    g_e[((size_t)s * B_ + b) * E_ + k] = sum * (1.0f / (float)F_);
}

// ---------------- tf32 tensor-core GEMM (unchanged from R3) ----------------
template<int BT, int RELU>
__global__ void __launch_bounds__(256) gemm_tf32(const float* __restrict__ A,
                                                 const float* __restrict__ Bm,
                                                 const float* __restrict__ bias,
                                                 float* __restrict__ C,
                                                 int M, int N, int K)
{
    __shared__ uint32_t As[16][136];
    __shared__ uint32_t Bs[16][136];

    const int tid  = threadIdx.x;
    const int lane = tid & 31;
    const int warp = tid >> 5;
    const int g    = lane >> 2;
    const int q    = lane & 3;
    const int wm0  = (warp >> 2) << 6;
    const int wn0  = (warp & 3) << 5;

    const int m0   = blockIdx.y << 7;
    const int n0   = blockIdx.x << 7;
    const int arow = tid >> 2, acol = (tid & 3) << 2;
    const int brow = tid >> 4, bcol = (tid & 15) << 3;

    float acc[4][4][4];
#pragma unroll
    for (int mi = 0; mi < 4; mi++)
#pragma unroll
        for (int ni = 0; ni < 4; ni++)
#pragma unroll
            for (int r = 0; r < 4; r++) acc[mi][ni][r] = 0.0f;

    const float* Ap0 = A + (size_t)(m0 + arow) * K + acol;
    const float* Ap1 = Ap0 + (size_t)64 * K;
    const float* Bp0; const float* Bp1 = 0;
    float4 a0 = *(const float4*)Ap0;
    float4 a1 = *(const float4*)Ap1;
    float4 b0, b1;
    if (BT) {
        Bp0 = Bm + (size_t)(n0 + arow) * K + acol;
        Bp1 = Bp0 + (size_t)64 * K;
        b0 = *(const float4*)Bp0;
        b1 = *(const float4*)Bp1;
    } else {
        Bp0 = Bm + (size_t)brow * N + n0 + bcol;
        b0 = *(const float4*)Bp0;
        b1 = *(const float4*)(Bp0 + 4);
    }

    const int nchunk = K >> 4;
    for (int ch = 0; ch < nchunk; ch++) {
        As[acol + 0][arow]      = f2tf32(a0.x); As[acol + 1][arow]      = f2tf32(a0.y);
        As[acol + 2][arow]      = f2tf32(a0.z); As[acol + 3][arow]      = f2tf32(a0.w);
        As[acol + 0][arow + 64] = f2tf32(a1.x); As[acol + 1][arow + 64] = f2tf32(a1.y);
        As[acol + 2][arow + 64] = f2tf32(a1.z); As[acol + 3][arow + 64] = f2tf32(a1.w);
        if (BT) {
            Bs[acol + 0][arow]      = f2tf32(b0.x); Bs[acol + 1][arow]      = f2tf32(b0.y);
            Bs[acol + 2][arow]      = f2tf32(b0.z); Bs[acol + 3][arow]      = f2tf32(b0.w);
            Bs[acol + 0][arow + 64] = f2tf32(b1.x); Bs[acol + 1][arow + 64] = f2tf32(b1.y);
            Bs[acol + 2][arow + 64] = f2tf32(b1.z); Bs[acol + 3][arow + 64] = f2tf32(b1.w);
        } else {
            uint4 u0 = make_uint4(f2tf32(b0.x), f2tf32(b0.y), f2tf32(b0.z), f2tf32(b0.w));
            uint4 u1 = make_uint4(f2tf32(b1.x), f2tf32(b1.y), f2tf32(b1.z), f2tf32(b1.w));
            *(uint4*)&Bs[brow][bcol]     = u0;
            *(uint4*)&Bs[brow][bcol + 4] = u1;
        }
        __syncthreads();

        if (ch + 1 < nchunk) {
            int ko = (ch + 1) << 4;
            a0 = *(const float4*)(Ap0 + ko);
            a1 = *(const float4*)(Ap1 + ko);
            if (BT) {
                b0 = *(const float4*)(Bp0 + ko);
                b1 = *(const float4*)(Bp1 + ko);
            } else {
                b0 = *(const float4*)(Bp0 + (size_t)ko * N);
                b1 = *(const float4*)(Bp0 + (size_t)ko * N + 4);
            }
        }

#pragma unroll
        for (int ks = 0; ks < 2; ks++) {
            const int kr = ks * 8 + q;
            uint32_t af[4][4], bf[4][2];
#pragma unroll
            for (int mi = 0; mi < 4; mi++) {
                int m = wm0 + mi * 16 + g;
                af[mi][0] = As[kr][m];
                af[mi][1] = As[kr][m + 8];
                af[mi][2] = As[kr + 4][m];
                af[mi][3] = As[kr + 4][m + 8];
            }
#pragma unroll
            for (int ni = 0; ni < 4; ni++) {
                int n = wn0 + ni * 8 + g;
                bf[ni][0] = Bs[kr][n];
                bf[ni][1] = Bs[kr + 4][n];
            }
#pragma unroll
            for (int mi = 0; mi < 4; mi++)
#pragma unroll
                for (int ni = 0; ni < 4; ni++)
                    mma_tf32(acc[mi][ni], af[mi], bf[ni]);
        }
        __syncthreads();
    }

#pragma unroll
    for (int ni = 0; ni < 4; ni++) {
        int cn = n0 + wn0 + ni * 8 + 2 * q;
        float bb0 = bias ? bias[cn]     : 0.0f;
        float bb1 = bias ? bias[cn + 1] : 0.0f;
#pragma unroll
        for (int mi = 0; mi < 4; mi++) {
            int r0 = m0 + wm0 + mi * 16 + g;
            float v0 = acc[mi][ni][0] + bb0;
            float v1 = acc[mi][ni][1] + bb1;
            float v2 = acc[mi][ni][2] + bb0;
            float v3 = acc[mi][ni][3] + bb1;
            if (RELU) {
                v0 = fmaxf(v0, 0.f); v1 = fmaxf(v1, 0.f);
                v2 = fmaxf(v2, 0.f); v3 = fmaxf(v3, 0.f);
            }
            *(float2*)&C[(size_t)r0 * N + cn]       = make_float2(v0, v1);
            *(float2*)&C[(size_t)(r0 + 8) * N + cn] = make_float2(v2, v3);
        }
    }
}

// ---------------- persistent fp16 tensor-core LSTM ----------------
// 128 CTAs x 128 threads (4 warps: wm = warp&1 over batch, wn = warp>>1 over n').
// CTA tile: 64 batch x 32 n' (gate-interleaved).  W fragments resident in REGISTERS
// (64 regs/thread, loaded once).  h kept fp16 in global [b][u]; per step it is copied
// into an XOR-swizzled smem tile and consumed via ldmatrix.x4.  Cell state c stays in
// registers for all 100 steps.  4 independent 32-CTA barriers (batch groups are
// independent recurrence chains).
__global__ void __launch_bounds__(128, 1) lstm_persist()
{
    __shared__ __align__(16) unsigned char Asm[64 * 512];   // h tile: 64 b x 256 k fp16, swizzled

    const int tid  = threadIdx.x;
    const int cta  = blockIdx.x;
    const int lane = tid & 31;
    const int warp = tid >> 5;
    const int g    = lane >> 2;
    const int q    = lane & 3;
    const int wm   = warp & 1;        // batch half within CTA (32b)
    const int wn   = warp >> 1;       // n' half within CTA (16 n')
    const int b0   = (cta & 3) << 6;  // batch base (4 groups)
    const int np0  = (cta >> 2) << 5; // n' base (32 groups)
    const int grp  = cta & 3;

    uint32_t smem_u32 = (uint32_t)__cvta_generic_to_shared(Asm);

    // ---- load W fragments into registers (once) ----
    uint32_t br[2][16][2];
#pragma unroll
    for (int nt = 0; nt < 2; nt++) {
        const int np = np0 + wn * 16 + nt * 8 + g;
        const float* wp = g_WhhP + (size_t)np * H_;
#pragma unroll
        for (int kc = 0; kc < 16; kc++) {
            float2 lo = *(const float2*)&wp[kc * 16 + 2 * q];
            float2 hi = *(const float2*)&wp[kc * 16 + 2 * q + 8];
            br[nt][kc][0] = packh2(lo.x, lo.y);
            br[nt][kc][1] = packh2(hi.x, hi.y);
        }
    }

    // ldmatrix address precompute (per m-tile)
    uint32_t abase[2]; int axor[2];
#pragma unroll
    for (int mt = 0; mt < 2; mt++) {
        int ar = wm * 32 + mt * 16 + (lane & 15);
        abase[mt] = smem_u32 + ar * 512;
        axor[mt]  = (ar & 7) << 4;
    }
    const int acol0 = (lane >> 4) * 16;

    float cst[2][2] = {{0.f, 0.f}, {0.f, 0.f}};   // cell state, fixed (b,u) per thread

    for (int s = 0; s <= T_; s++) {
        const int prv = s & 1;

        // ---- Gx prefetch (DRAM; hidden under the mma loop) ----
        float2 gxv[2][2][2];
#pragma unroll
        for (int mt = 0; mt < 2; mt++)
#pragma unroll
            for (int nt = 0; nt < 2; nt++) {
                if (s < T_) {
                    const int bg = b0 + wm * 32 + mt * 16 + g;
                    const int nc = np0 + wn * 16 + nt * 8 + 2 * q;
                    const float* gp = g_Gx + ((size_t)s * B_ + bg) * G4 + nc;
                    gxv[mt][nt][0] = *(const float2*)gp;
                    gxv[mt][nt][1] = *(const float2*)(gp + (size_t)8 * G4);
                } else {
                    gxv[mt][nt][0] = make_float2(0.f, 0.f);
                    gxv[mt][nt][1] = make_float2(0.f, 0.f);
                }
            }

        // ---- A-fill: copy h tile (fp16) global -> swizzled smem ----
        {
            const __half* hp = g_hF[prv];
#pragma unroll
            for (int it = 0; it < 16; it++) {
                int id  = tid + it * 128;     // 0..2047 16B units
                int row = id >> 5;
                int cu  = id & 31;
                uint4 v = __ldcg((const uint4*)&hp[(size_t)(b0 + row) * H_ + cu * 8]);
                int off = row * 512 + ((cu * 16) ^ ((row & 7) << 4));
                *(uint4*)(Asm + off) = v;
            }
        }
        __syncthreads();

        // ---- mma mainloop: acc[b-tile][n-tile] += h . W^T ----
        float acc[2][2][4];
#pragma unroll
        for (int mt = 0; mt < 2; mt++)
#pragma unroll
            for (int nt = 0; nt < 2; nt++)
#pragma unroll
                for (int r = 0; r < 4; r++) acc[mt][nt][r] = 0.f;

#pragma unroll
        for (int kc = 0; kc < 16; kc++) {
            uint32_t a0[4], a1[4];
            ldmx4(a0, abase[0] + (((acol0 + kc * 32)) ^ axor[0]));
            ldmx4(a1, abase[1] + (((acol0 + kc * 32)) ^ axor[1]));
            mma_f16(acc[0][0], a0, br[0][kc]);
            mma_f16(acc[0][1], a0, br[1][kc]);
            mma_f16(acc[1][0], a1, br[0][kc]);
            mma_f16(acc[1][1], a1, br[1][kc]);
        }

        if (s < T_) {
            // ---- gate epilogue (register-resident, one shfl exchange) ----
            const int hi = q & 1;
            __half* hnxt = g_hF[prv ^ 1];
#pragma unroll
            for (int mt = 0; mt < 2; mt++)
#pragma unroll
                for (int nt = 0; nt < 2; nt++) {
                    float p0 = acc[mt][nt][0] + gxv[mt][nt][0].x;
                    float p1 = acc[mt][nt][1] + gxv[mt][nt][0].y;
                    float p2 = acc[mt][nt][2] + gxv[mt][nt][1].x;
                    float p3 = acc[mt][nt][3] + gxv[mt][nt][1].y;
                    float r0 = __shfl_xor_sync(0xffffffffu, p0, 1);
                    float r1 = __shfl_xor_sync(0xffffffffu, p1, 1);
                    float r2 = __shfl_xor_sync(0xffffffffu, p2, 1);
                    float r3 = __shfl_xor_sync(0xffffffffu, p3, 1);
                    float gi = hi ? r2 : p0;
                    float gf = hi ? r3 : p1;
                    float gg = hi ? p2 : r0;
                    float go = hi ? p3 : r1;
                    float c  = sigmf(gf) * cst[mt][nt] + sigmf(gi) * tanhf(gg);
                    cst[mt][nt] = c;
                    float h  = sigmf(go) * tanhf(c);
                    const int b = b0 + wm * 32 + mt * 16 + g + (hi ? 8 : 0);
                    const int u = (np0 >> 2) + wn * 4 + nt * 2 + (q >> 1);
                    hnxt[(size_t)b * H_ + u] = __float2half_rn(h);
                }

            // ---- per-group grid barrier ----
            __threadfence();
            __syncthreads();
            if (tid == 0) {
                int snap = g_gen4[grp];
                int old  = atomicAdd(&g_cnt4[grp], 1);
                if (old == 31) {
                    g_cnt4[grp] = 0;
                    __threadfence();
                    g_gen4[grp] = snap + 1;
                } else {
                    while (g_gen4[grp] == snap) { __nanosleep(32); }
                    __threadfence();
                }
            }
            __syncthreads();
        } else {
            // ---- s == 100: export r = hN @ W^T (raw preacts) and cN ----
#pragma unroll
            for (int mt = 0; mt < 2; mt++)
#pragma unroll
                for (int nt = 0; nt < 2; nt++) {
                    const int bg = b0 + wm * 32 + mt * 16 + g;
                    const int nc = np0 + wn * 16 + nt * 8 + 2 * q;
                    *(float2*)&g_r[(size_t)bg * G4 + nc] =
                        make_float2(acc[mt][nt][0], acc[mt][nt][1]);
                    *(float2*)&g_r[(size_t)(bg + 8) * G4 + nc] =
                        make_float2(acc[mt][nt][2], acc[mt][nt][3]);
                    const int b = bg + ((q & 1) ? 8 : 0);
                    const int u = (np0 >> 2) + wn * 4 + nt * 2 + (q >> 1);
                    g_c[(size_t)b * H_ + u] = cst[mt][nt];
                }
        }
    }
}

// ---------------- tgt positions: parallel single LSTM step from (hN, cN) ----------------
__global__ void tgt_gates()
{
    int row = blockIdx.x;            // t*256 + b
    int tt = row >> 8, b = row & 255;
    int j = threadIdx.x;
    float4 gv = *(const float4*)&g_Gx[((size_t)(tt + T_) * B_ + b) * G4 + (j << 2)];
    float4 rv = *(const float4*)&g_r[b * G4 + (j << 2)];
    float gi = gv.x + rv.x, gf = gv.y + rv.y, gg = gv.z + rv.z, go = gv.w + rv.w;
    float c = sigmf(gf) * g_c[b * H_ + j] + sigmf(gi) * tanhf(gg);
    g_Hout[(size_t)row * H_ + j] = sigmf(go) * tanhf(c);
}

// ---------------- final: out = sigmoid(Z2 @ W3 + b3), remap (t,b) -> (b,t) ----------------
__global__ void final_dot(const float* __restrict__ W3, const float* __restrict__ b3,
                          float* __restrict__ out)
{
    int row  = blockIdx.x * 8 + (threadIdx.x >> 5);
    int lane = threadIdx.x & 31;
    float4 z = *(const float4*)&g_Z2[row * P2_ + lane * 4];
    float4 w = *(const float4*)&W3[lane * 4];
    float s = z.x * w.x + z.y * w.y + z.z * w.z + z.w * w.w;
#pragma unroll
    for (int o = 16; o > 0; o >>= 1) s += __shfl_xor_sync(0xffffffffu, s, o);
    if (lane == 0) {
        int tt = row >> 8, b = row & 255;
        out[b * T_ + tt] = 1.0f / (1.0f + expf(-(s + b3[0])));
    }
}

// ---------------- launcher ----------------
extern "C" void kernel_launch(void* const* d_in, const int* in_sizes, int n_in,
                              void* d_out, int out_size)
{
    const int*   x    = (const int*)  d_in[0];
    const float* emb  = (const float*)d_in[1];
    const float* Wih  = (const float*)d_in[2];
    const float* Whh  = (const float*)d_in[3];
    const float* bih  = (const float*)d_in[4];
    const float* bhh  = (const float*)d_in[5];
    const float* W1   = (const float*)d_in[6];
    const float* b1   = (const float*)d_in[7];
    const float* W2   = (const float*)d_in[8];
    const float* b2   = (const float*)d_in[9];
    const float* W3   = (const float*)d_in[10];
    const float* b3   = (const float*)d_in[11];
    float* out = (float*)d_out;

    void *pe, *pGx, *pWihP, *pbias, *pHout, *pZ1, *pZ2;
    cudaGetSymbolAddress(&pe,    g_e);
    cudaGetSymbolAddress(&pGx,   g_Gx);
    cudaGetSymbolAddress(&pWihP, g_WihP);
    cudaGetSymbolAddress(&pbias, g_biasP);
    cudaGetSymbolAddress(&pHout, g_Hout);
    cudaGetSymbolAddress(&pZ1,   g_Z1);
    cudaGetSymbolAddress(&pZ2,   g_Z2);

    // prep
    permute_weights<<<G4, 256>>>(Wih, Whh, bih, bhh);
    zero_h0<<<(B_ * H_ / 2 + 255) / 256, 256>>>();
    embed_mean<<<B_ * S_, E_>>>(x, emb);

    // x-part for all 200 positions (tensor cores), biases folded in
    gemm_tf32<1, 0><<<dim3(G4 / 128, (S_ * B_) / 128), 256>>>(
        (const float*)pe, (const float*)pWihP, (const float*)pbias, (float*)pGx,
        S_ * B_, G4, E_);

    // ALL 100 LSTM steps + r = hN@W in one persistent fp16 tensor-core kernel
    lstm_persist<<<128, 128>>>();

    // parallel gates for the 100 tgt positions
    tgt_gates<<<T_ * B_, 256>>>();

    // MLP (tensor cores)
    gemm_tf32<0, 1><<<dim3(P1_ / 128, (T_ * B_) / 128), 256>>>(
        (const float*)pHout, W1, b1, (float*)pZ1, T_ * B_, P1_, H_);
    gemm_tf32<0, 1><<<dim3(P2_ / 128, (T_ * B_) / 128), 256>>>(
        (const float*)pZ1, W2, b2, (float*)pZ2, T_ * B_, P2_, P1_);

    // head + layout remap to (B, T)
    final_dot<<<(T_ * B_) / 8, 256>>>(W3, b3, out);
}

// round 5
// speedup vs baseline: 3.1658x; 1.1048x over previous
#include <cuda_runtime.h>
#include <cuda_fp16.h>
#include <math.h>
#include <stdint.h>

// Problem dims
#define B_   256
#define S_   200
#define T_   100
#define F_   10
#define E_   128
#define H_   256
#define G4   1024   // 4*H
#define P1_  512
#define P2_  128

// persistent LSTM config
#define LCTA 64
#define LTHR 256
#define LGRP 16     // CTAs per batch group

// ---------------- scratch (device globals; no runtime alloc allowed) ----------------
__device__ __half g_eh  [S_*B_*E_];           // e fp16, [s][b][k]
__device__ float  g_Gx  [(size_t)S_*B_*G4];   // x-part + biases, gate-interleaved [s][b][n']
__device__ __half g_WihPh[G4*E_];             // permuted fp16 [n'][k]
__device__ float  g_WhhP[G4*H_];              // permuted fp32 [n'][k] (LSTM reg frags)
__device__ float  g_biasP[G4];
__device__ __half g_W1h[P1_*H_];              // [n][k] fp16
__device__ __half g_W2h[P2_*P1_];             // [n][k] fp16
__device__ __half g_hF[2][B_*H_];             // hidden state fp16 [b][u], ping-pong
__device__ float  g_c[B_*H_];                 // final cN, [b][unit]
__device__ float  g_r[B_*G4];                 // hN @ WhhP^T, [b][n']
__device__ __half g_HoutH[T_*B_*H_];          // fp16 (MLP1 A operand)
__device__ __half g_Z1h[(size_t)T_*B_*P1_];   // fp16 (MLP2 A operand)
__device__ float  g_Z2[T_*B_*P2_];

// per-group barrier, each counter on its own 128B line
struct __align__(256) BarT { int cnt; int pad0[31]; int gen; int pad1[31]; };
__device__ BarT g_bar[4];

__device__ __forceinline__ float sigmf(float x) { return 1.0f / (1.0f + expf(-x)); }

__device__ __forceinline__ void mma_f16(float* d, const uint32_t* a, const uint32_t* b)
{
    asm volatile(
        "mma.sync.aligned.m16n8k16.row.col.f32.f16.f16.f32 "
        "{%0,%1,%2,%3}, {%4,%5,%6,%7}, {%8,%9}, {%0,%1,%2,%3};\n"
        : "+f"(d[0]), "+f"(d[1]), "+f"(d[2]), "+f"(d[3])
        : "r"(a[0]), "r"(a[1]), "r"(a[2]), "r"(a[3]), "r"(b[0]), "r"(b[1]));
}

__device__ __forceinline__ void ldmx4(uint32_t* r, uint32_t addr)
{
    asm volatile(
        "ldmatrix.sync.aligned.m8n8.x4.shared.b16 {%0,%1,%2,%3}, [%4];\n"
        : "=r"(r[0]), "=r"(r[1]), "=r"(r[2]), "=r"(r[3]) : "r"(addr));
}

__device__ __forceinline__ uint32_t packh2(float lo, float hi)
{
    __half2 h = __floats2half2_rn(lo, hi);
    return *reinterpret_cast<uint32_t*>(&h);
}

// swizzled offset for [128 rows][32 halfs] tiles packed 2 rows per 128B, 16B units
__device__ __forceinline__ int swz16(int r, int u)
{
    return (r >> 1) * 128 + (((((r & 1) << 2) | u) ^ ((r >> 1) & 7)) << 4);
}

// ---------------- small prep kernels ----------------
__global__ void permute_weights(const float* __restrict__ Wih, const float* __restrict__ Whh,
                                const float* __restrict__ bih, const float* __restrict__ bhh)
{
    int np  = blockIdx.x;                 // n' 0..1023
    int src = (np & 3) * H_ + (np >> 2);  // gate*256 + unit
    int t   = threadIdx.x;
    if (t < E_) g_WihPh[np * E_ + t] = __float2half_rn(Wih[src * E_ + t]);
    g_WhhP[np * H_ + t] = Whh[src * H_ + t];
    if (t == 0) g_biasP[np] = bih[src] + bhh[src];
}

__global__ void prep_w1(const float* __restrict__ W1)   // (H,P1) -> [P1][H] fp16
{
    int n = blockIdx.x, k = threadIdx.x;               // 512 blocks x 256 thr
    g_W1h[n * H_ + k] = __float2half_rn(W1[k * P1_ + n]);
}

__global__ void prep_w2(const float* __restrict__ W2)   // (P1,P2) -> [P2][P1] fp16
{
    int n = blockIdx.x, k = threadIdx.x;               // 128 blocks x 512 thr
    g_W2h[n * P1_ + k] = __float2half_rn(W2[k * P2_ + n]);
}

__global__ void zero_h0()
{
    int i = blockIdx.x * 256 + threadIdx.x;
    if (i < (B_ * H_) / 2) ((uint32_t*)g_hF[0])[i] = 0;
}

__global__ void embed_mean(const int* __restrict__ x, const float* __restrict__ emb)
{
    int row = blockIdx.x;            // b*S_ + s
    int b = row / S_, s = row % S_;
    const int* xi = x + row * F_;
    int k = threadIdx.x;
    float sum = 0.0f;
#pragma unroll
    for (int f = 0; f < F_; f++) sum += emb[(size_t)xi[f] * E_ + k];
    g_eh[((size_t)s * B_ + b) * E_ + k] = __float2half_rn(sum * (1.0f / (float)F_));
}

// ---------------- fp16 tensor-core GEMM: C = act(A @ B^T + bias) ----------------
// A: (M,K) fp16 row-major.  Bh: (N,K) fp16 row-major ([n][k], ldmatrix-native).
// CTA tile 128x128, k-chunk 32, 256 thr = 8 warps (2m x 4n), warp tile 64x32.
// OUTH=1 -> C is fp16, else fp32.  Requires M%128==0, N%128==0, K%32==0.
template<int RELU, int OUTH>
__global__ void __launch_bounds__(256) gemm_f16(const __half* __restrict__ A,
                                                const __half* __restrict__ Bh,
                                                const float* __restrict__ bias,
                                                void* __restrict__ Cv,
                                                int M, int N, int K)
{
    __shared__ __align__(16) __half As[128 * 32];
    __shared__ __align__(16) __half Bs[128 * 32];

    const int tid  = threadIdx.x;
    const int lane = tid & 31;
    const int warp = tid >> 5;
    const int g    = lane >> 2;
    const int q    = lane & 3;
    const int wm0  = (warp >> 2) << 6;
    const int wn0  = (warp & 3) << 5;
    const int m0   = blockIdx.y << 7;
    const int n0   = blockIdx.x << 7;

    const uint32_t As32 = (uint32_t)__cvta_generic_to_shared(As);
    const uint32_t Bs32 = (uint32_t)__cvta_generic_to_shared(Bs);

    const int lr = tid >> 2;          // loader row (0..63), +64 on second beat
    const int lu = tid & 3;           // loader 16B unit

    const __half* Ag0 = A  + (size_t)(m0 + lr) * K + lu * 8;
    const __half* Ag1 = Ag0 + (size_t)64 * K;
    const __half* Bg0 = Bh + (size_t)(n0 + lr) * K + lu * 8;
    const __half* Bg1 = Bg0 + (size_t)64 * K;

    float acc[4][4][4];
#pragma unroll
    for (int mi = 0; mi < 4; mi++)
#pragma unroll
        for (int ni = 0; ni < 4; ni++)
#pragma unroll
            for (int r = 0; r < 4; r++) acc[mi][ni][r] = 0.0f;

    uint4 pa0 = *(const uint4*)Ag0;
    uint4 pa1 = *(const uint4*)Ag1;
    uint4 pb0 = *(const uint4*)Bg0;
    uint4 pb1 = *(const uint4*)Bg1;

    const int nchunk = K >> 5;
    for (int ch = 0; ch < nchunk; ch++) {
        *(uint4*)((char*)As + swz16(lr,      lu)) = pa0;
        *(uint4*)((char*)As + swz16(lr + 64, lu)) = pa1;
        *(uint4*)((char*)Bs + swz16(lr,      lu)) = pb0;
        *(uint4*)((char*)Bs + swz16(lr + 64, lu)) = pb1;
        __syncthreads();

        if (ch + 1 < nchunk) {
            int ko = (ch + 1) << 5;
            pa0 = *(const uint4*)(Ag0 + ko);
            pa1 = *(const uint4*)(Ag1 + ko);
            pb0 = *(const uint4*)(Bg0 + ko);
            pb1 = *(const uint4*)(Bg1 + ko);
        }

#pragma unroll
        for (int ks = 0; ks < 2; ks++) {
            const int fu = ks * 2 + (lane >> 4);
            const int fr = lane & 15;
            uint32_t af[4][4], bf[4][2];
#pragma unroll
            for (int mt = 0; mt < 4; mt++)
                ldmx4(af[mt], As32 + swz16(wm0 + mt * 16 + fr, fu));
#pragma unroll
            for (int np = 0; np < 2; np++) {
                uint32_t t[4];
                ldmx4(t, Bs32 + swz16(wn0 + np * 16 + fr, fu));
                bf[2 * np][0]     = t[0];
                bf[2 * np + 1][0] = t[1];
                bf[2 * np][1]     = t[2];
                bf[2 * np + 1][1] = t[3];
            }
#pragma unroll
            for (int mt = 0; mt < 4; mt++)
#pragma unroll
                for (int nt = 0; nt < 4; nt++)
                    mma_f16(acc[mt][nt], af[mt], bf[nt]);
        }
        __syncthreads();
    }

    // epilogue
#pragma unroll
    for (int nt = 0; nt < 4; nt++) {
        int cn = n0 + wn0 + nt * 8 + 2 * q;
        float bb0 = bias[cn], bb1 = bias[cn + 1];
#pragma unroll
        for (int mt = 0; mt < 4; mt++) {
            int r0 = m0 + wm0 + mt * 16 + g;
            float v0 = acc[mt][nt][0] + bb0;
            float v1 = acc[mt][nt][1] + bb1;
            float v2 = acc[mt][nt][2] + bb0;
            float v3 = acc[mt][nt][3] + bb1;
            if (RELU) {
                v0 = fmaxf(v0, 0.f); v1 = fmaxf(v1, 0.f);
                v2 = fmaxf(v2, 0.f); v3 = fmaxf(v3, 0.f);
            }
            if (OUTH) {
                __half* Ch = (__half*)Cv;
                *(__half2*)&Ch[(size_t)r0 * N + cn]       = __floats2half2_rn(v0, v1);
                *(__half2*)&Ch[(size_t)(r0 + 8) * N + cn] = __floats2half2_rn(v2, v3);
            } else {
                float* Cf = (float*)Cv;
                *(float2*)&Cf[(size_t)r0 * N + cn]       = make_float2(v0, v1);
                *(float2*)&Cf[(size_t)(r0 + 8) * N + cn] = make_float2(v2, v3);
            }
        }
    }
}

// ---------------- persistent fp16 tensor-core LSTM ----------------
// 64 CTAs x 256 thr (8 warps: wm=warp&1 over 32b, wn=warp>>1 over 16n').
// CTA tile 64b x 64n'.  W frags in registers.  16-CTA per-group barriers with
// padded lines + acq_rel atomics.  h stores staged via smem -> 128 uint4 STG.
__global__ void __launch_bounds__(LTHR, 1) lstm_persist()
{
    __shared__ __align__(16) unsigned char Asm[64 * 512];   // h tile 64b x 256k fp16, swizzled
    __shared__ __align__(16) __half hstg[64 * 16];          // h staging (2KB)

    const int tid  = threadIdx.x;
    const int cta  = blockIdx.x;
    const int lane = tid & 31;
    const int warp = tid >> 5;
    const int g    = lane >> 2;
    const int q    = lane & 3;
    const int wm   = warp & 1;        // batch half (32b)
    const int wn   = warp >> 1;       // n' quarter (16 n')
    const int b0   = (cta & 3) << 6;  // batch base
    const int np0  = (cta >> 2) << 6; // n' base (64 per CTA)
    const int grp  = cta & 3;
    const int u0   = np0 >> 2;        // unit base (16 per CTA)

    uint32_t smem_u32 = (uint32_t)__cvta_generic_to_shared(Asm);

    // ---- W fragments into registers (once) ----
    uint32_t br[2][16][2];
#pragma unroll
    for (int nt = 0; nt < 2; nt++) {
        const int np = np0 + wn * 16 + nt * 8 + g;
        const float* wp = g_WhhP + (size_t)np * H_;
#pragma unroll
        for (int kc = 0; kc < 16; kc++) {
            float2 lo = *(const float2*)&wp[kc * 16 + 2 * q];
            float2 hi = *(const float2*)&wp[kc * 16 + 2 * q + 8];
            br[nt][kc][0] = packh2(lo.x, lo.y);
            br[nt][kc][1] = packh2(hi.x, hi.y);
        }
    }

    uint32_t abase[2]; int axor[2];
#pragma unroll
    for (int mt = 0; mt < 2; mt++) {
        int ar = wm * 32 + mt * 16 + (lane & 15);
        abase[mt] = smem_u32 + ar * 512;
        axor[mt]  = (ar & 7) << 4;
    }
    const int acol0 = (lane >> 4) * 16;

    float cst[2][2] = {{0.f, 0.f}, {0.f, 0.f}};

    for (int s = 0; s <= T_; s++) {
        const int prv = s & 1;

        // Gx prefetch (fp32, DRAM)
        float2 gxv[2][2][2];
#pragma unroll
        for (int mt = 0; mt < 2; mt++)
#pragma unroll
            for (int nt = 0; nt < 2; nt++) {
                if (s < T_) {
                    const int bg = b0 + wm * 32 + mt * 16 + g;
                    const int nc = np0 + wn * 16 + nt * 8 + 2 * q;
                    const float* gp = g_Gx + ((size_t)s * B_ + bg) * G4 + nc;
                    gxv[mt][nt][0] = *(const float2*)gp;
                    gxv[mt][nt][1] = *(const float2*)(gp + (size_t)8 * G4);
                } else {
                    gxv[mt][nt][0] = make_float2(0.f, 0.f);
                    gxv[mt][nt][1] = make_float2(0.f, 0.f);
                }
            }

        // A-fill: h tile global -> swizzled smem (L2 reads)
        {
            const __half* hp = g_hF[prv];
#pragma unroll
            for (int it = 0; it < 8; it++) {
                int id  = tid + it * LTHR;    // 0..2047 16B units
                int row = id >> 5;
                int cu  = id & 31;
                uint4 v = __ldcg((const uint4*)&hp[(size_t)(b0 + row) * H_ + cu * 8]);
                int off = row * 512 + ((cu * 16) ^ ((row & 7) << 4));
                *(uint4*)(Asm + off) = v;
            }
        }
        __syncthreads();

        // mma mainloop
        float acc[2][2][4];
#pragma unroll
        for (int mt = 0; mt < 2; mt++)
#pragma unroll
            for (int nt = 0; nt < 2; nt++)
#pragma unroll
                for (int r = 0; r < 4; r++) acc[mt][nt][r] = 0.f;

#pragma unroll
        for (int kc = 0; kc < 16; kc++) {
            uint32_t a0[4], a1[4];
            ldmx4(a0, abase[0] + ((acol0 + kc * 32) ^ axor[0]));
            ldmx4(a1, abase[1] + ((acol0 + kc * 32) ^ axor[1]));
            mma_f16(acc[0][0], a0, br[0][kc]);
            mma_f16(acc[0][1], a0, br[1][kc]);
            mma_f16(acc[1][0], a1, br[0][kc]);
            mma_f16(acc[1][1], a1, br[1][kc]);
        }

        if (s < T_) {
            // gates (register-resident, one shfl exchange); h -> smem staging
            const int hi = q & 1;
#pragma unroll
            for (int mt = 0; mt < 2; mt++)
#pragma unroll
                for (int nt = 0; nt < 2; nt++) {
                    float p0 = acc[mt][nt][0] + gxv[mt][nt][0].x;
                    float p1 = acc[mt][nt][1] + gxv[mt][nt][0].y;
                    float p2 = acc[mt][nt][2] + gxv[mt][nt][1].x;
                    float p3 = acc[mt][nt][3] + gxv[mt][nt][1].y;
                    float r0 = __shfl_xor_sync(0xffffffffu, p0, 1);
                    float r1 = __shfl_xor_sync(0xffffffffu, p1, 1);
                    float r2 = __shfl_xor_sync(0xffffffffu, p2, 1);
                    float r3 = __shfl_xor_sync(0xffffffffu, p3, 1);
                    float gi = hi ? r2 : p0;
                    float gf = hi ? r3 : p1;
                    float gg = hi ? p2 : r0;
                    float go = hi ? p3 : r1;
                    float c  = sigmf(gf) * cst[mt][nt] + sigmf(gi) * tanhf(gg);
                    cst[mt][nt] = c;
                    float h  = sigmf(go) * tanhf(c);
                    const int bl = wm * 32 + mt * 16 + g + (hi ? 8 : 0);
                    const int ul = wn * 4 + nt * 2 + (q >> 1);
                    hstg[bl * 16 + ul] = __float2half_rn(h);
                }
            __syncthreads();

            // coalesced h store: 128 x uint4
            __half* hnxt = g_hF[prv ^ 1];
            if (tid < 128) {
                int row = tid >> 1, seg = tid & 1;
                *(uint4*)&hnxt[(size_t)(b0 + row) * H_ + u0 + seg * 8] =
                    *(uint4*)&hstg[row * 16 + seg * 8];
                __threadfence();
            }
            __syncthreads();

            // per-group barrier (padded lines, acq_rel atomics)
            if (tid == 0) {
                int snap, old;
                asm volatile("ld.acquire.gpu.global.b32 %0, [%1];"
                             : "=r"(snap) : "l"(&g_bar[grp].gen) : "memory");
                asm volatile("atom.acq_rel.gpu.global.add.s32 %0, [%1], %2;"
                             : "=r"(old) : "l"(&g_bar[grp].cnt), "r"(1) : "memory");
                if (old == LGRP - 1) {
                    g_bar[grp].cnt = 0;
                    asm volatile("st.release.gpu.global.b32 [%0], %1;"
                                 :: "l"(&g_bar[grp].gen), "r"(snap + 1) : "memory");
                } else {
                    int cur;
                    while (true) {
                        asm volatile("ld.acquire.gpu.global.b32 %0, [%1];"
                                     : "=r"(cur) : "l"(&g_bar[grp].gen) : "memory");
                        if (cur != snap) break;
                        __nanosleep(20);
                    }
                }
            }
            __syncthreads();
        } else {
            // s == 100: export r = hN @ W^T and cN
#pragma unroll
            for (int mt = 0; mt < 2; mt++)
#pragma unroll
                for (int nt = 0; nt < 2; nt++) {
                    const int bg = b0 + wm * 32 + mt * 16 + g;
                    const int nc = np0 + wn * 16 + nt * 8 + 2 * q;
                    *(float2*)&g_r[(size_t)bg * G4 + nc] =
                        make_float2(acc[mt][nt][0], acc[mt][nt][1]);
                    *(float2*)&g_r[(size_t)(bg + 8) * G4 + nc] =
                        make_float2(acc[mt][nt][2], acc[mt][nt][3]);
                    const int b = bg + ((q & 1) ? 8 : 0);
                    const int u = u0 + wn * 4 + nt * 2 + (q >> 1);
                    g_c[(size_t)b * H_ + u] = cst[mt][nt];
                }
        }
    }
}

// ---------------- tgt positions: parallel single LSTM step from (hN, cN) ----------------
__global__ void tgt_gates()
{
    int row = blockIdx.x;            // t*256 + b
    int tt = row >> 8, b = row & 255;
    int j = threadIdx.x;
    float4 gv = *(const float4*)&g_Gx[((size_t)(tt + T_) * B_ + b) * G4 + (j << 2)];
    float4 rv = *(const float4*)&g_r[b * G4 + (j << 2)];
    float gi = gv.x + rv.x, gf = gv.y + rv.y, gg = gv.z + rv.z, go = gv.w + rv.w;
    float c = sigmf(gf) * g_c[b * H_ + j] + sigmf(gi) * tanhf(gg);
    g_HoutH[(size_t)row * H_ + j] = __float2half_rn(sigmf(go) * tanhf(c));
}

// ---------------- final: out = sigmoid(Z2 @ W3 + b3), remap (t,b) -> (b,t) ----------------
__global__ void final_dot(const float* __restrict__ W3, const float* __restrict__ b3,
                          float* __restrict__ out)
{
    int row  = blockIdx.x * 8 + (threadIdx.x >> 5);
    int lane = threadIdx.x & 31;
    float4 z = *(const float4*)&g_Z2[row * P2_ + lane * 4];
    float4 w = *(const float4*)&W3[lane * 4];
    float s = z.x * w.x + z.y * w.y + z.z * w.z + z.w * w.w;
#pragma unroll
    for (int o = 16; o > 0; o >>= 1) s += __shfl_xor_sync(0xffffffffu, s, o);
    if (lane == 0) {
        int tt = row >> 8, b = row & 255;
        out[b * T_ + tt] = 1.0f / (1.0f + expf(-(s + b3[0])));
    }
}

// ---------------- launcher ----------------
extern "C" void kernel_launch(void* const* d_in, const int* in_sizes, int n_in,
                              void* d_out, int out_size)
{
    const int*   x    = (const int*)  d_in[0];
    const float* emb  = (const float*)d_in[1];
    const float* Wih  = (const float*)d_in[2];
    const float* Whh  = (const float*)d_in[3];
    const float* bih  = (const float*)d_in[4];
    const float* bhh  = (const float*)d_in[5];
    const float* W1   = (const float*)d_in[6];
    const float* b1   = (const float*)d_in[7];
    const float* W2   = (const float*)d_in[8];
    const float* b2   = (const float*)d_in[9];
    const float* W3   = (const float*)d_in[10];
    const float* b3   = (const float*)d_in[11];
    float* out = (float*)d_out;

    void *peh, *pGx, *pWihPh, *pbias, *pHoutH, *pZ1h, *pZ2, *pW1h, *pW2h;
    cudaGetSymbolAddress(&peh,    g_eh);
    cudaGetSymbolAddress(&pGx,    g_Gx);
    cudaGetSymbolAddress(&pWihPh, g_WihPh);
    cudaGetSymbolAddress(&pbias,  g_biasP);
    cudaGetSymbolAddress(&pHoutH, g_HoutH);
    cudaGetSymbolAddress(&pZ1h,   g_Z1h);
    cudaGetSymbolAddress(&pZ2,    g_Z2);
    cudaGetSymbolAddress(&pW1h,   g_W1h);
    cudaGetSymbolAddress(&pW2h,   g_W2h);

    // prep
    permute_weights<<<G4, 256>>>(Wih, Whh, bih, bhh);
    prep_w1<<<P1_, H_>>>(W1);
    prep_w2<<<P2_, P1_>>>(W2);
    zero_h0<<<(B_ * H_ / 2 + 255) / 256, 256>>>();
    embed_mean<<<B_ * S_, E_>>>(x, emb);

    // x-part for all 200 positions (fp16 tensor cores), biases folded in
    gemm_f16<0, 0><<<dim3(G4 / 128, (S_ * B_) / 128), 256>>>(
        (const __half*)peh, (const __half*)pWihPh, (const float*)pbias, pGx,
        S_ * B_, G4, E_);

    // ALL 100 LSTM steps + r = hN@W in one persistent kernel
    lstm_persist<<<LCTA, LTHR>>>();

    // parallel gates for the 100 tgt positions
    tgt_gates<<<T_ * B_, 256>>>();

    // MLP (fp16 tensor cores)
    gemm_f16<1, 1><<<dim3(P1_ / 128, (T_ * B_) / 128), 256>>>(
        (const __half*)pHoutH, (const __half*)pW1h, b1, pZ1h, T_ * B_, P1_, H_);
    gemm_f16<1, 0><<<dim3(P2_ / 128, (T_ * B_) / 128), 256>>>(
        (const __half*)pZ1h, (const __half*)pW2h, b2, pZ2, T_ * B_, P2_, P1_);

    // head + layout remap to (B, T)
    final_dot<<<(T_ * B_) / 8, 256>>>(W3, b3, out);
}